// round 17
// baseline (speedup 1.0000x reference)
#include <cuda_runtime.h>
#include <cuda_fp16.h>
#include <cstdint>

#define NB 4
#define HH 128
#define WWD 128
#define CC 256
#define NDIL 16
#define DF 8
#define CATC 384
#define HW (HH*WWD)
#define NPIX (NB*HW)
#define EPSF 1e-3f

// ---------------- scratch (static device globals: allocation-free) ----------------
__device__ float g_x32[(size_t)NPIX*CC];
__device__ __half g_hf[(size_t)NPIX*CATC];
__device__ float g_dx [(size_t)NDIL*NPIX*DF];
__device__ float g_kq [(size_t)NDIL*NB*DF*HW];
__device__ float g_v  [(size_t)NDIL*NPIX*DF];
__device__ float g_pre [(size_t)NPIX*CC];    // xn-channel partial
__device__ float g_pre2[(size_t)NPIX*CC];    // attn-channel partial
__device__ float g_smax[NDIL*NB*DF];
__device__ float g_sinv[NDIL*NB*DF];
__device__ __half g_Wh[(size_t)9*256*384];

// ---------------- stream kit ----------------
namespace {
struct StreamKit {
    cudaStream_t s1;
    cudaEvent_t eFork, eW, eD, eP1;
    StreamKit(){
        int lo = 0, hi = 0;
        cudaDeviceGetStreamPriorityRange(&lo, &hi);   // hi = highest priority
        cudaStreamCreateWithPriority(&s1, cudaStreamNonBlocking, hi);
        cudaEventCreateWithFlags(&eFork, cudaEventDisableTiming);
        cudaEventCreateWithFlags(&eW,    cudaEventDisableTiming);
        cudaEventCreateWithFlags(&eD,    cudaEventDisableTiming);
        cudaEventCreateWithFlags(&eP1,   cudaEventDisableTiming);
    }
};
StreamKit g_sk;
}

// ---------------- f32x2 helpers ----------------
__device__ __forceinline__ unsigned long long dup2(float f){
    unsigned long long r; unsigned u = __float_as_uint(f);
    asm("mov.b64 %0, {%1, %1};" : "=l"(r) : "r"(u));
    return r;
}
__device__ __forceinline__ unsigned long long ffma2(unsigned long long a, unsigned long long b, unsigned long long c){
    unsigned long long d;
    asm("fma.rn.f32x2 %0, %1, %2, %3;" : "=l"(d) : "l"(a), "l"(b), "l"(c));
    return d;
}
__device__ __forceinline__ float2 unpk(unsigned long long v){
    unsigned lo, hi;
    asm("mov.b64 {%0, %1}, %2;" : "=r"(lo), "=r"(hi) : "l"(v));
    return make_float2(__uint_as_float(lo), __uint_as_float(hi));
}

// ---------------- warp MMA + cp.async plumbing ----------------
__device__ __forceinline__ uint32_t smem_u32(const void* p){
    uint32_t a;
    asm("{ .reg .u64 t; cvta.to.shared.u64 t, %1; cvt.u32.u64 %0, t; }" : "=r"(a) : "l"(p));
    return a;
}
__device__ __forceinline__ void ldsm4(uint32_t* r, uint32_t addr){
    asm volatile("ldmatrix.sync.aligned.m8n8.x4.shared.b16 {%0,%1,%2,%3}, [%4];"
        : "=r"(r[0]), "=r"(r[1]), "=r"(r[2]), "=r"(r[3]) : "r"(addr));
}
__device__ __forceinline__ void mma16816h(float* c, const uint32_t* a, const uint32_t* b){
    asm volatile("mma.sync.aligned.m16n8k16.row.col.f32.f16.f16.f32 "
        "{%0,%1,%2,%3}, {%4,%5,%6,%7}, {%8,%9}, {%0,%1,%2,%3};"
        : "+f"(c[0]), "+f"(c[1]), "+f"(c[2]), "+f"(c[3])
        : "r"(a[0]), "r"(a[1]), "r"(a[2]), "r"(a[3]), "r"(b[0]), "r"(b[1]));
}
__device__ __forceinline__ void cpa16(uint32_t dst, const void* src, uint32_t srcsize){
    asm volatile("cp.async.cg.shared.global [%0], [%1], 16, %2;"
        :: "r"(dst), "l"(src), "r"(srcsize) : "memory");
}
#define CP_COMMIT() asm volatile("cp.async.commit_group;" ::: "memory")
#define CP_WAIT1()  asm volatile("cp.async.wait_group 1;" ::: "memory")
#define CP_WAIT0()  asm volatile("cp.async.wait_group 0;" ::: "memory")

__device__ __forceinline__ void store_h8(__half* hp, const float* v){
    __half hh[8];
    #pragma unroll
    for (int j=0;j<8;j++) hh[j] = __float2half_rn(v[j]);
    *(uint4*)hp = *(uint4*)hh;
}

// ---------------- K0: weight prep ----------------
__global__ __launch_bounds__(256) void k_wprep(const float* __restrict__ W){
    int idx = blockIdx.x*256 + threadIdx.x;
    int oc = idx & 255;
    int rest = idx >> 8;
    int ch = rest % 384, tap = rest / 384;
    float w = W[idx];
    size_t o = ((size_t)(tap*256 + oc))*384 + ch;
    g_Wh[o] = __float2half_rn(w);
}

// ---------------- K1: input LayerNorm ----------------
__global__ __launch_bounds__(256) void k_ln_in(const float* __restrict__ x,
                                               const float* __restrict__ gg, const float* __restrict__ bb){
    int gw = (blockIdx.x*blockDim.x + threadIdx.x) >> 5;
    int lane = threadIdx.x & 31;
    if (gw >= NPIX) return;
    const float4* sp = (const float4*)(x + (size_t)gw*CC);
    float4 a0 = sp[lane*2], a1 = sp[lane*2+1];
    float s = a0.x+a0.y+a0.z+a0.w + a1.x+a1.y+a1.z+a1.w;
    #pragma unroll
    for (int o=16;o;o>>=1) s += __shfl_xor_sync(0xffffffffu, s, o);
    float m = s * (1.0f/256.0f);
    float d[8] = {a0.x-m,a0.y-m,a0.z-m,a0.w-m,a1.x-m,a1.y-m,a1.z-m,a1.w-m};
    float q = 0.f;
    #pragma unroll
    for (int j=0;j<8;j++) q += d[j]*d[j];
    #pragma unroll
    for (int o=16;o;o>>=1) q += __shfl_xor_sync(0xffffffffu, q, o);
    float r = rsqrtf(q*(1.0f/256.0f) + EPSF);
    const float4* gp = (const float4*)gg; const float4* bp = (const float4*)bb;
    float4 g0 = gp[lane*2], g1 = gp[lane*2+1];
    float4 b0 = bp[lane*2], b1 = bp[lane*2+1];
    float gv[8] = {g0.x,g0.y,g0.z,g0.w,g1.x,g1.y,g1.z,g1.w};
    float bv[8] = {b0.x,b0.y,b0.z,b0.w,b1.x,b1.y,b1.z,b1.w};
    float o[8];
    #pragma unroll
    for (int j=0;j<8;j++) o[j] = d[j]*r*gv[j] + bv[j];
    float* dp = g_x32 + (size_t)gw*CC + lane*8;
    *(float4*)dp = make_float4(o[0],o[1],o[2],o[3]);
    *(float4*)(dp+4) = make_float4(o[4],o[5],o[6],o[7]);
    store_h8(g_hf + (size_t)gw*CATC + lane*8, o);
}

// ---------------- output: sum partials + bias + relu + LayerNorm -> out ----------------
__global__ __launch_bounds__(256) void k_ln_out(const float* __restrict__ bias,
                                                const float* __restrict__ gg, const float* __restrict__ bb,
                                                float* __restrict__ out){
    int gw = (blockIdx.x*blockDim.x + threadIdx.x) >> 5;
    int lane = threadIdx.x & 31;
    if (gw >= NPIX) return;
    const float4* p1 = (const float4*)(g_pre  + (size_t)gw*CC) + lane*2;
    const float4* p2 = (const float4*)(g_pre2 + (size_t)gw*CC) + lane*2;
    const float4* bi = (const float4*)bias + lane*2;
    float v[8];
    {
        float4 a0 = p1[0], a1 = p1[1];
        float4 c0 = p2[0], c1 = p2[1];
        float4 e0 = bi[0], e1 = bi[1];
        v[0]=fmaxf(a0.x+c0.x+e0.x,0.f); v[1]=fmaxf(a0.y+c0.y+e0.y,0.f);
        v[2]=fmaxf(a0.z+c0.z+e0.z,0.f); v[3]=fmaxf(a0.w+c0.w+e0.w,0.f);
        v[4]=fmaxf(a1.x+c1.x+e1.x,0.f); v[5]=fmaxf(a1.y+c1.y+e1.y,0.f);
        v[6]=fmaxf(a1.z+c1.z+e1.z,0.f); v[7]=fmaxf(a1.w+c1.w+e1.w,0.f);
    }
    float s = 0.f;
    #pragma unroll
    for (int j=0;j<8;j++) s += v[j];
    #pragma unroll
    for (int o=16;o;o>>=1) s += __shfl_xor_sync(0xffffffffu, s, o);
    float m = s * (1.0f/256.0f);
    float q = 0.f;
    #pragma unroll
    for (int j=0;j<8;j++){ float dd = v[j]-m; q += dd*dd; }
    #pragma unroll
    for (int o=16;o;o>>=1) q += __shfl_xor_sync(0xffffffffu, q, o);
    float r = rsqrtf(q*(1.0f/256.0f) + EPSF);
    const float4* gp = (const float4*)gg; const float4* bp = (const float4*)bb;
    float4 g0 = gp[lane*2], g1 = gp[lane*2+1];
    float4 b0 = bp[lane*2], b1 = bp[lane*2+1];
    float gv[8] = {g0.x,g0.y,g0.z,g0.w,g1.x,g1.y,g1.z,g1.w};
    float bv[8] = {b0.x,b0.y,b0.z,b0.w,b1.x,b1.y,b1.z,b1.w};
    float o[8];
    #pragma unroll
    for (int j=0;j<8;j++) o[j] = (v[j]-m)*r*gv[j] + bv[j];
    float* dp = out + (size_t)gw*CC + lane*8;
    *(float4*)dp     = make_float4(o[0],o[1],o[2],o[3]);
    *(float4*)(dp+4) = make_float4(o[4],o[5],o[6],o[7]);
}

// ---------------- K2: 1x1 down conv (256 -> 8), 4 branches per CTA, relu, f32x2 ----------------
__global__ __launch_bounds__(256) void k_dwn(const float* __restrict__ Wd, const float* __restrict__ Bd){
    __shared__ __align__(16) float ws[4*CC*DF];
    __shared__ float xs[8][512];
    const int i0 = blockIdx.x * 4;
    const int px0 = blockIdx.y * 512;
    const int t = threadIdx.x;

    const float4* wsrc = (const float4*)(Wd + (size_t)i0*CC*DF);
    for (int idx = t; idx < 4*CC*DF/4; idx += 256) ((float4*)ws)[idx] = wsrc[idx];

    unsigned long long acc[4][2][4];
    #pragma unroll
    for (int br=0;br<4;br++)
        #pragma unroll
        for (int j=0;j<2;j++)
            #pragma unroll
            for (int k=0;k<4;k++) acc[br][j][k] = 0ull;

    for (int cc = 0; cc < CC; cc += 8){
        __syncthreads();
        #pragma unroll
        for (int j = 0; j < 2; j++){
            int p = t + 256*j;
            const float* src = g_x32 + (size_t)(px0 + p)*CC + cc;
            float4 v0 = *(const float4*)src;
            float4 v1 = *(const float4*)(src+4);
            xs[0][p]=v0.x; xs[1][p]=v0.y; xs[2][p]=v0.z; xs[3][p]=v0.w;
            xs[4][p]=v1.x; xs[5][p]=v1.y; xs[6][p]=v1.z; xs[7][p]=v1.w;
        }
        __syncthreads();
        #pragma unroll
        for (int c = 0; c < 8; c++){
            unsigned long long xd0 = dup2(xs[c][t]), xd1 = dup2(xs[c][t+256]);
            #pragma unroll
            for (int br = 0; br < 4; br++){
                const unsigned long long* wp = (const unsigned long long*)&ws[br*CC*DF + (cc+c)*8];
                unsigned long long w0=wp[0], w1=wp[1], w2=wp[2], w3=wp[3];
                acc[br][0][0]=ffma2(xd0,w0,acc[br][0][0]); acc[br][0][1]=ffma2(xd0,w1,acc[br][0][1]);
                acc[br][0][2]=ffma2(xd0,w2,acc[br][0][2]); acc[br][0][3]=ffma2(xd0,w3,acc[br][0][3]);
                acc[br][1][0]=ffma2(xd1,w0,acc[br][1][0]); acc[br][1][1]=ffma2(xd1,w1,acc[br][1][1]);
                acc[br][1][2]=ffma2(xd1,w2,acc[br][1][2]); acc[br][1][3]=ffma2(xd1,w3,acc[br][1][3]);
            }
        }
    }
    #pragma unroll
    for (int br = 0; br < 4; br++){
        float bb[8];
        #pragma unroll
        for (int oc=0;oc<8;oc++) bb[oc] = Bd[(i0+br)*8+oc];
        #pragma unroll
        for (int j=0;j<2;j++){
            int p = px0 + t + 256*j;
            float o[8];
            #pragma unroll
            for (int k=0;k<4;k++){
                float2 f = unpk(acc[br][j][k]);
                o[2*k]   = fmaxf(f.x + bb[2*k],   0.f);
                o[2*k+1] = fmaxf(f.y + bb[2*k+1], 0.f);
            }
            float* dp = g_dx + ((size_t)(i0+br)*NPIX + p)*DF;
            *(float4*)dp     = make_float4(o[0],o[1],o[2],o[3]);
            *(float4*)(dp+4) = make_float4(o[4],o[5],o[6],o[7]);
        }
    }
}

// ---------------- K3: k,q,v 3x3 dilated convs + relu + kq product ----------------
__global__ __launch_bounds__(64) void k_kqv(const float* __restrict__ Kw, const float* __restrict__ Kb,
                                            const float* __restrict__ Qw, const float* __restrict__ Qb,
                                            const float* __restrict__ Vw, const float* __restrict__ Vb){
    __shared__ float xs[3][8][128];
    __shared__ float wsk[576], wsq[576], wsv[576];
    __shared__ float sbk[8], sbq[8], sbv[8];

    const int h = blockIdx.x, n = blockIdx.y, i = blockIdx.z;
    const int d = i + 1;
    const int t = threadIdx.x;

    const float* dxb = g_dx + ((size_t)i*NPIX + (size_t)n*HW)*DF;
    #pragma unroll
    for (int r = 0; r < 3; r++){
        int hh = h + (r-1)*d;
        if ((unsigned)hh < (unsigned)HH){
            #pragma unroll
            for (int j = 0; j < 2; j++){
                int w = t + 64*j;
                const float* src = dxb + (size_t)(hh*WWD + w)*DF;
                float4 v0 = *(const float4*)src;
                float4 v1 = *(const float4*)(src+4);
                xs[r][0][w]=v0.x; xs[r][1][w]=v0.y; xs[r][2][w]=v0.z; xs[r][3][w]=v0.w;
                xs[r][4][w]=v1.x; xs[r][5][w]=v1.y; xs[r][6][w]=v1.z; xs[r][7][w]=v1.w;
            }
        } else {
            for (int idx = t; idx < 8*128; idx += 64) (&xs[r][0][0])[idx] = 0.f;
        }
    }
    for (int idx = t; idx < 576; idx += 64){
        wsk[idx] = Kw[(size_t)i*576 + idx];
        wsq[idx] = Qw[(size_t)i*576 + idx];
        wsv[idx] = Vw[(size_t)i*576 + idx];
    }
    if (t < 8){ sbk[t]=Kb[i*8+t]; sbq[t]=Qb[i*8+t]; sbv[t]=Vb[i*8+t]; }
    __syncthreads();

    const int w0 = t, w1 = t + 64;
    float ak0[8], ak1[8], aq0[8], aq1[8], av0[8], av1[8];
    #pragma unroll
    for (int c=0;c<8;c++){ ak0[c]=ak1[c]=aq0[c]=aq1[c]=av0[c]=av1[c]=0.f; }

    #pragma unroll 1
    for (int tap = 0; tap < 9; tap++){
        int ky = tap/3, kx = tap%3;
        int c0 = w0 + (kx-1)*d; bool ok0 = (unsigned)c0 < (unsigned)WWD;
        int c1 = w1 + (kx-1)*d; bool ok1 = (unsigned)c1 < (unsigned)WWD;
        const float* xr = &xs[ky][0][0];
        #pragma unroll
        for (int ci = 0; ci < 8; ci++){
            float x0 = ok0 ? xr[ci*128 + c0] : 0.f;
            float x1 = ok1 ? xr[ci*128 + c1] : 0.f;
            const float* wk = &wsk[(tap*8+ci)*8];
            const float* wq = &wsq[(tap*8+ci)*8];
            const float* wv = &wsv[(tap*8+ci)*8];
            #pragma unroll
            for (int co = 0; co < 8; co++){
                ak0[co] += x0*wk[co]; ak1[co] += x1*wk[co];
                aq0[co] += x0*wq[co]; aq1[co] += x1*wq[co];
                av0[co] += x0*wv[co]; av1[co] += x1*wv[co];
            }
        }
    }

    float kq0[8], kq1[8], vv0[8], vv1[8];
    #pragma unroll
    for (int co = 0; co < 8; co++){
        float k0 = fmaxf(ak0[co]+sbk[co],0.f), k1 = fmaxf(ak1[co]+sbk[co],0.f);
        float q0 = fmaxf(aq0[co]+sbq[co],0.f), q1 = fmaxf(aq1[co]+sbq[co],0.f);
        vv0[co]  = fmaxf(av0[co]+sbv[co],0.f); vv1[co] = fmaxf(av1[co]+sbv[co],0.f);
        kq0[co] = k0*q0; kq1[co] = k1*q1;
    }
    const int in = i*NB + n;
    const int hwb = h*WWD;
    #pragma unroll
    for (int co = 0; co < 8; co++){
        float* kp = g_kq + ((size_t)in*DF + co)*HW + hwb;
        kp[w0] = kq0[co]; kp[w1] = kq1[co];
    }
    float* vp0 = g_v + ((size_t)i*NPIX + (size_t)n*HW + hwb + w0)*DF;
    float* vp1 = g_v + ((size_t)i*NPIX + (size_t)n*HW + hwb + w1)*DF;
    *(float4*)vp0     = make_float4(vv0[0],vv0[1],vv0[2],vv0[3]);
    *(float4*)(vp0+4) = make_float4(vv0[4],vv0[5],vv0[6],vv0[7]);
    *(float4*)vp1     = make_float4(vv1[0],vv1[1],vv1[2],vv1[3]);
    *(float4*)(vp1+4) = make_float4(vv1[4],vv1[5],vv1[6],vv1[7]);
}

// ---------------- K4: softmax stats ----------------
__global__ __launch_bounds__(256) void k_softstats(){
    const int plane = blockIdx.x;
    const float4* p = (const float4*)(g_kq + (size_t)plane*HW);
    const int t = threadIdx.x, lane = t & 31, warp = t >> 5;
    __shared__ float red[8];

    float m = -1e30f;
    for (int idx = t; idx < HW/4; idx += 256){
        float4 v = p[idx];
        m = fmaxf(m, fmaxf(fmaxf(v.x,v.y), fmaxf(v.z,v.w)));
    }
    #pragma unroll
    for (int o=16;o;o>>=1) m = fmaxf(m, __shfl_xor_sync(0xffffffffu, m, o));
    if (lane==0) red[warp] = m;
    __syncthreads();
    float bm = red[0];
    #pragma unroll
    for (int k=1;k<8;k++) bm = fmaxf(bm, red[k]);
    __syncthreads();

    float s = 0.f;
    for (int idx = t; idx < HW/4; idx += 256){
        float4 v = p[idx];
        s += __expf(v.x-bm) + __expf(v.y-bm) + __expf(v.z-bm) + __expf(v.w-bm);
    }
    #pragma unroll
    for (int o=16;o;o>>=1) s += __shfl_xor_sync(0xffffffffu, s, o);
    if (lane==0) red[warp] = s;
    __syncthreads();
    if (t == 0){
        float tot = 0.f;
        #pragma unroll
        for (int k=0;k<8;k++) tot += red[k];
        g_smax[plane] = bm;
        g_sinv[plane] = 1.0f / tot;
    }
}

// ---------------- K5: softmax*v + LN over DF -> fp16 cat channels ----------------
__global__ __launch_bounds__(256) void k_attn_ln(const float* __restrict__ gup, const float* __restrict__ bup){
    __shared__ float sm[8], si[8], sg[8], sb[8];
    const int in = blockIdx.y;
    const int t = threadIdx.x;
    if (t < 8){ sm[t]=g_smax[in*DF+t]; si[t]=g_sinv[in*DF+t]; sg[t]=gup[t]; sb[t]=bup[t]; }
    __syncthreads();
    const int hw = blockIdx.x*256 + t;
    const int i = in >> 2, n = in & 3;

    size_t vb = ((size_t)i*NPIX + (size_t)n*HW + hw)*DF;
    float4 v0 = *(const float4*)&g_v[vb];
    float4 v1 = *(const float4*)&g_v[vb+4];
    float vv[8] = {v0.x,v0.y,v0.z,v0.w,v1.x,v1.y,v1.z,v1.w};

    float y[8]; float s = 0.f;
    #pragma unroll
    for (int c = 0; c < 8; c++){
        float kq = g_kq[((size_t)in*DF + c)*HW + hw];
        float a = __expf(kq - sm[c]) * si[c];
        y[c] = a * vv[c];
        s += y[c];
    }
    float mean = s * 0.125f, q = 0.f;
    #pragma unroll
    for (int c = 0; c < 8; c++){ float dd = y[c]-mean; q += dd*dd; }
    float r = rsqrtf(q*0.125f + EPSF);
    float o[8];
    #pragma unroll
    for (int c = 0; c < 8; c++) o[c] = (y[c]-mean)*r*sg[c] + sb[c];

    size_t ob = ((size_t)(n*HW + hw))*CATC + CC + i*DF;
    store_h8(g_hf + ob, o);
}

// ---------------- K6: smooth 3x3 conv 384->256, HMMA fp16, independent partials ----------------
#define BUF_BYTES 32768
#define K6_SMEM (1024 + 2*BUF_BYTES)

template<int NSTAGE, int CCDIV, int CCBASE>
__global__ void __launch_bounds__(256, 2) k_smooth_part(float* __restrict__ dst){
    extern __shared__ __align__(128) char smem[];
    const uint32_t sb0 = smem_u32(smem) + 1024;

    const int t = threadIdx.x;
    const int lane = t & 31, wid = t >> 5;
    const int wm = wid & 3, wn = wid >> 2;
    const int row_id = blockIdx.x;
    const int n = row_id >> 7, h = row_id & 127;
    const int oc0 = blockIdx.y * 128;

    const int srow = t >> 1;
    const int cb   = (t & 1) * 4;

    uint32_t dsw[4];
    #pragma unroll
    for (int j = 0; j < 4; j++){
        uint32_t off = (uint32_t)srow*128 + (uint32_t)(cb + j)*16;
        dsw[j] = off ^ ((off >> 3) & 0x70);
    }

    auto stage_issue = [&](int s, int b){
        const int tap = s / CCDIV, cc = CCBASE + (s % CCDIV) * 64;
        const int dy = tap/3 - 1, dxo = tap%3 - 1;
        const int hh = h + dy;
        const int ww = srow + dxo;
        const bool ok = ((unsigned)hh < (unsigned)HH) && ((unsigned)ww < (unsigned)WWD);
        const int hcl = ok ? hh : 0, wcl = ok ? ww : 0;
        const uint32_t sz = ok ? 16u : 0u;
        const uint32_t base = sb0 + (uint32_t)b*BUF_BYTES;
        const size_t abase = ((size_t)((n*HH + hcl)*WWD + wcl))*CATC + cc + cb*8;
        const size_t wbase = ((size_t)(tap*256 + oc0 + srow))*CATC + cc + cb*8;
        #pragma unroll
        for (int j = 0; j < 4; j++){
            cpa16(base +         dsw[j], g_hf + abase + j*8, sz);
            cpa16(base + 16384 + dsw[j], g_Wh + wbase + j*8, 16u);
        }
        CP_COMMIT();
    };

    const int pix0 = row_id * 128;
    float acc[2][8][4];
    #pragma unroll
    for (int a=0;a<2;a++)
        #pragma unroll
        for (int b=0;b<8;b++)
            #pragma unroll
            for (int c=0;c<4;c++) acc[a][b][c] = 0.f;

    stage_issue(0, 0);

    #pragma unroll 1
    for (int s = 0; s < NSTAGE; s++){
        if (s + 1 < NSTAGE){
            stage_issue(s + 1, (s + 1) & 1);
            CP_WAIT1();
        } else {
            CP_WAIT0();
        }
        __syncthreads();

        const uint32_t base = sb0 + (uint32_t)(s & 1)*BUF_BYTES;
        const uint32_t aB = base, bB = base + 16384;

        #pragma unroll
        for (int ks = 0; ks < 4; ks++){
            uint32_t ah[2][4];
            #pragma unroll
            for (int mt = 0; mt < 2; mt++){
                uint32_t arow = (uint32_t)(wm*32 + mt*16 + (lane & 15));
                uint32_t ac16 = (uint32_t)(ks*2 + (lane >> 4));
                uint32_t off = arow*128 + ac16*16;
                uint32_t sw = off ^ ((off >> 3) & 0x70);
                ldsm4(ah[mt], aB + sw);
            }
            uint32_t brow = (uint32_t)(wn*64 + ((lane >> 4) << 3) + (lane & 7));
            uint32_t bc16 = (uint32_t)(ks*2 + ((lane >> 3) & 1));
            #pragma unroll
            for (int g = 0; g < 4; g++){
                uint32_t off = (brow + (uint32_t)g*16)*128 + bc16*16;
                uint32_t sw = off ^ ((off >> 3) & 0x70);
                uint32_t bfr[4];
                ldsm4(bfr, bB + sw);
                mma16816h(acc[0][2*g],   ah[0], bfr);
                mma16816h(acc[1][2*g],   ah[1], bfr);
                mma16816h(acc[0][2*g+1], ah[0], bfr+2);
                mma16816h(acc[1][2*g+1], ah[1], bfr+2);
            }
        }
        __syncthreads();
    }

    // Epilogue: raw partial accumulators -> dst
    #pragma unroll
    for (int mt = 0; mt < 2; mt++){
        #pragma unroll
        for (int nt = 0; nt < 8; nt++){
            int r = wm*32 + mt*16 + (lane >> 2);
            int cidx = wn*64 + nt*8 + (lane & 3)*2;
            float* p0 = dst + (size_t)(pix0 + r)*CC + oc0 + cidx;
            float* p1 = dst + (size_t)(pix0 + r + 8)*CC + oc0 + cidx;
            *(float2*)p0 = make_float2(acc[mt][nt][0], acc[mt][nt][1]);
            *(float2*)p1 = make_float2(acc[mt][nt][2], acc[mt][nt][3]);
        }
    }
}

// ---------------- launch ----------------
extern "C" void kernel_launch(void* const* d_in, const int* in_sizes, int n_in,
                              void* d_out, int out_size){
    (void)in_sizes; (void)n_in; (void)out_size;
    const float* x        = (const float*)d_in[0];
    const float* dwn_w    = (const float*)d_in[1];
    const float* dwn_b    = (const float*)d_in[2];
    const float* k_w      = (const float*)d_in[3];
    const float* k_b      = (const float*)d_in[4];
    const float* q_w      = (const float*)d_in[5];
    const float* q_b      = (const float*)d_in[6];
    const float* v_w      = (const float*)d_in[7];
    const float* v_b      = (const float*)d_in[8];
    const float* smooth_w = (const float*)d_in[9];
    const float* smooth_b = (const float*)d_in[10];
    const float* ln_in_g  = (const float*)d_in[11];
    const float* ln_in_b  = (const float*)d_in[12];
    const float* ln_up_g  = (const float*)d_in[13];
    const float* ln_up_b  = (const float*)d_in[14];
    const float* ln_out_g = (const float*)d_in[15];
    const float* ln_out_b = (const float*)d_in[16];
    float* out = (float*)d_out;

    float* d_pre;  cudaGetSymbolAddress((void**)&d_pre,  g_pre);
    float* d_pre2; cudaGetSymbolAddress((void**)&d_pre2, g_pre2);

    cudaFuncSetAttribute(k_smooth_part<36,4,0>,
                         cudaFuncAttributeMaxDynamicSharedMemorySize, K6_SMEM);
    cudaFuncSetAttribute(k_smooth_part<18,2,256>,
                         cudaFuncAttributeMaxDynamicSharedMemorySize, K6_SMEM);

    // fork: s1 joins capture via event recorded on origin stream first
    cudaEventRecord(g_sk.eFork, 0);
    cudaStreamWaitEvent(g_sk.s1, g_sk.eFork, 0);

    // s1 (HIGH prio): weight prep
    k_wprep<<<9*384, 256, 0, g_sk.s1>>>(smooth_w);
    cudaEventRecord(g_sk.eW, g_sk.s1);

    // origin: input LN, then down-conv at full machine speed
    k_ln_in<<<NPIX/8, 256>>>(x, ln_in_g, ln_in_b);
    k_dwn<<<dim3(NDIL/4, NPIX/512), 256>>>(dwn_w, dwn_b);
    cudaEventRecord(g_sk.eD, 0);

    // s1: p1 (xn partial -> g_pre), after dwn (serialize heavy DRAM phases)
    cudaStreamWaitEvent(g_sk.s1, g_sk.eD, 0);
    k_smooth_part<36,4,0><<<dim3(NB*HH, 2), 256, K6_SMEM, g_sk.s1>>>(d_pre);
    cudaEventRecord(g_sk.eP1, g_sk.s1);

    // origin: rest of attention chain, then p2 (attn partial -> g_pre2), overlapping p1
    k_kqv<<<dim3(HH, NB, NDIL), 64>>>(k_w, k_b, q_w, q_b, v_w, v_b);
    k_softstats<<<NDIL*NB*DF, 256>>>();
    k_attn_ln<<<dim3(HW/256, NDIL*NB), 256>>>(ln_up_g, ln_up_b);
    cudaStreamWaitEvent(0, g_sk.eW, 0);
    k_smooth_part<18,2,256><<<dim3(NB*HH, 2), 256, K6_SMEM>>>(d_pre2);

    // join: final sum + bias + relu + LN
    cudaStreamWaitEvent(0, g_sk.eP1, 0);
    k_ln_out<<<NPIX/8, 256>>>(smooth_b, ln_out_g, ln_out_b, out);
}